// round 3
// baseline (speedup 1.0000x reference)
#include <cuda_runtime.h>
#include <math.h>

#define T_TOK 4096
#define H_DIM 2048
#define I_DIM 2048
#define N_EXP 16
#define TOPK  2

#define BM 64
#define BN 64
#define BK 16

// ---------------- routing scratch (device globals: no allocation allowed) ---
__device__ int   g_count[N_EXP];
__device__ int   g_cursor[N_EXP];
__device__ int   g_offset[N_EXP + 1];
__device__ int   g_tids[T_TOK * TOPK];   // per-token chosen expert ids
__device__ float g_tw[T_TOK * TOPK];     // per-token normalized weights
__device__ int   g_tok[T_TOK * TOPK];    // compacted row -> token
__device__ float g_cf[T_TOK * TOPK];     // compacted row -> coef
__device__ float g_h[(size_t)T_TOK * TOPK * I_DIM];  // 64 MB hidden scratch

// ---------------- init ------------------------------------------------------
__global__ void zero_kernel(float* __restrict__ out) {
    size_t idx = (size_t)blockIdx.x * blockDim.x + threadIdx.x;
    size_t stride = (size_t)gridDim.x * blockDim.x;
    for (size_t i = idx; i < (size_t)T_TOK * H_DIM; i += stride) out[i] = 0.0f;
    if (idx < N_EXP) g_count[idx] = 0;
}

// ---------------- gating: logits -> softmax top-2 -> normalized weights -----
__global__ void gate_kernel(const float* __restrict__ x,
                            const float* __restrict__ gw) {
    int t    = blockIdx.x;
    int tid  = threadIdx.x;
    int w    = tid >> 5;
    int lane = tid & 31;
    __shared__ float logits[N_EXP];

    const float* xr = x + (size_t)t * H_DIM;
    int e0 = 2 * w, e1 = 2 * w + 1;
    const float* gr0 = gw + (size_t)e0 * H_DIM;
    const float* gr1 = gw + (size_t)e1 * H_DIM;
    float a0 = 0.f, a1 = 0.f;
    for (int h = lane; h < H_DIM; h += 32) {
        float xv = xr[h];
        a0 += xv * gr0[h];
        a1 += xv * gr1[h];
    }
#pragma unroll
    for (int o = 16; o; o >>= 1) {
        a0 += __shfl_down_sync(0xFFFFFFFFu, a0, o);
        a1 += __shfl_down_sync(0xFFFFFFFFu, a1, o);
    }
    if (lane == 0) { logits[e0] = a0; logits[e1] = a1; }
    __syncthreads();

    if (tid == 0) {
        // top-1 (strict > keeps lowest index on ties, matching lax.top_k)
        int   b0 = 0;
        float v0 = logits[0];
        for (int e = 1; e < N_EXP; e++)
            if (logits[e] > v0) { v0 = logits[e]; b0 = e; }
        int   b1 = -1;
        float v1 = -3.4e38f;
        for (int e = 0; e < N_EXP; e++) {
            if (e == b0) continue;
            if (logits[e] > v1) { v1 = logits[e]; b1 = e; }
        }
        // normalized top-2 softmax weights: w0 = 1/(1+exp(l1-l0))
        float w0 = 1.0f / (1.0f + expf(v1 - v0));
        float w1 = 1.0f - w0;
        g_tids[2 * t]     = b0;
        g_tids[2 * t + 1] = b1;
        g_tw[2 * t]       = w0;
        g_tw[2 * t + 1]   = w1;
        atomicAdd(&g_count[b0], 1);
        atomicAdd(&g_count[b1], 1);
    }
}

// ---------------- prefix scan over 16 expert counts -------------------------
__global__ void scan_kernel() {
    if (threadIdx.x == 0) {
        int s = 0;
        for (int e = 0; e < N_EXP; e++) {
            g_offset[e] = s;
            s += g_count[e];
            g_cursor[e] = 0;
        }
        g_offset[N_EXP] = s;
    }
}

// ---------------- build compacted (token, coef) lists per expert ------------
__global__ void scatter_kernel() {
    int t = blockIdx.x * blockDim.x + threadIdx.x;
    if (t >= T_TOK) return;
#pragma unroll
    for (int k = 0; k < TOPK; k++) {
        int   e   = g_tids[2 * t + k];
        float wv  = g_tw[2 * t + k];
        int   pos = atomicAdd(&g_cursor[e], 1);
        int   r   = g_offset[e] + pos;
        g_tok[r] = t;
        g_cf[r]  = wv;
    }
}

// ---------------- GEMM1: h = silu(x@Wg^T) * (x@Wu^T) per expert -------------
__global__ __launch_bounds__(256) void gemm1_kernel(const float* __restrict__ x,
                                                    const float* __restrict__ ws) {
    int e    = blockIdx.z;
    int base = g_offset[e];
    int cnt  = g_offset[e + 1] - base;
    int m0   = blockIdx.y * BM;
    if (m0 >= cnt) return;
    int n0 = blockIdx.x * BN;

    __shared__ float As[BK][BM];
    __shared__ float B1s[BK][BN];
    __shared__ float B2s[BK][BN];

    int tid  = threadIdx.x;
    int tx   = tid & 15;
    int ty   = tid >> 4;
    int lrow = tid >> 2;          // 0..63
    int kc   = (tid & 3) * 4;     // 0,4,8,12

    int arow_ok = (m0 + lrow) < cnt;
    int token   = arow_ok ? g_tok[base + m0 + lrow] : 0;

    const float* aptr  = x + (size_t)token * H_DIM + kc;
    const float* b1ptr = ws + ((size_t)e * 2 * I_DIM + (n0 + lrow)) * H_DIM + kc;
    const float* b2ptr = ws + ((size_t)e * 2 * I_DIM + I_DIM + (n0 + lrow)) * H_DIM + kc;

    float4 ra  = arow_ok ? *(const float4*)aptr : make_float4(0, 0, 0, 0);
    float4 rb1 = *(const float4*)b1ptr;
    float4 rb2 = *(const float4*)b2ptr;

    float cg[4][4] = {};
    float cu[4][4] = {};

    const int KT = H_DIM / BK;
    for (int kt = 0; kt < KT; kt++) {
        As[kc + 0][lrow] = ra.x;  As[kc + 1][lrow] = ra.y;
        As[kc + 2][lrow] = ra.z;  As[kc + 3][lrow] = ra.w;
        B1s[kc + 0][lrow] = rb1.x; B1s[kc + 1][lrow] = rb1.y;
        B1s[kc + 2][lrow] = rb1.z; B1s[kc + 3][lrow] = rb1.w;
        B2s[kc + 0][lrow] = rb2.x; B2s[kc + 1][lrow] = rb2.y;
        B2s[kc + 2][lrow] = rb2.z; B2s[kc + 3][lrow] = rb2.w;
        __syncthreads();

        if (kt + 1 < KT) {   // prefetch next K-tile while computing this one
            int off = (kt + 1) * BK;
            ra  = arow_ok ? *(const float4*)(aptr + off) : make_float4(0, 0, 0, 0);
            rb1 = *(const float4*)(b1ptr + off);
            rb2 = *(const float4*)(b2ptr + off);
        }

#pragma unroll
        for (int k = 0; k < BK; k++) {
            float4 a  = *(const float4*)&As[k][ty * 4];
            float4 b1 = *(const float4*)&B1s[k][tx * 4];
            float4 b2 = *(const float4*)&B2s[k][tx * 4];
            float av[4]  = {a.x, a.y, a.z, a.w};
            float bv1[4] = {b1.x, b1.y, b1.z, b1.w};
            float bv2[4] = {b2.x, b2.y, b2.z, b2.w};
#pragma unroll
            for (int i = 0; i < 4; i++)
#pragma unroll
                for (int j = 0; j < 4; j++) {
                    cg[i][j] += av[i] * bv1[j];
                    cu[i][j] += av[i] * bv2[j];
                }
        }
        __syncthreads();
    }

#pragma unroll
    for (int i = 0; i < 4; i++) {
        int ml = ty * 4 + i;
        if (m0 + ml < cnt) {
            int r = base + m0 + ml;
            float res[4];
#pragma unroll
            for (int j = 0; j < 4; j++) {
                float g = cg[i][j];
                float u = cu[i][j];
                float s = 1.0f / (1.0f + expf(-g));
                res[j] = g * s * u;
            }
            *(float4*)&g_h[(size_t)r * I_DIM + n0 + tx * 4] =
                make_float4(res[0], res[1], res[2], res[3]);
        }
    }
}

// ---------------- GEMM2: out[token] += coef * (h @ W2^T) --------------------
__global__ __launch_bounds__(256) void gemm2_kernel(const float* __restrict__ w2s,
                                                    float* __restrict__ out) {
    int e    = blockIdx.z;
    int base = g_offset[e];
    int cnt  = g_offset[e + 1] - base;
    int m0   = blockIdx.y * BM;
    if (m0 >= cnt) return;
    int n0 = blockIdx.x * BN;

    __shared__ float As[BK][BM];
    __shared__ float Bs[BK][BN];

    int tid  = threadIdx.x;
    int tx   = tid & 15;
    int ty   = tid >> 4;
    int lrow = tid >> 2;
    int kc   = (tid & 3) * 4;

    int arow_ok = (m0 + lrow) < cnt;
    int arow    = arow_ok ? (base + m0 + lrow) : base;

    const float* aptr = g_h + (size_t)arow * I_DIM + kc;
    const float* bptr = w2s + ((size_t)e * H_DIM + (n0 + lrow)) * I_DIM + kc;

    float4 ra = arow_ok ? *(const float4*)aptr : make_float4(0, 0, 0, 0);
    float4 rb = *(const float4*)bptr;

    float c[4][4] = {};

    const int KT = I_DIM / BK;
    for (int kt = 0; kt < KT; kt++) {
        As[kc + 0][lrow] = ra.x; As[kc + 1][lrow] = ra.y;
        As[kc + 2][lrow] = ra.z; As[kc + 3][lrow] = ra.w;
        Bs[kc + 0][lrow] = rb.x; Bs[kc + 1][lrow] = rb.y;
        Bs[kc + 2][lrow] = rb.z; Bs[kc + 3][lrow] = rb.w;
        __syncthreads();

        if (kt + 1 < KT) {
            int off = (kt + 1) * BK;
            ra = arow_ok ? *(const float4*)(aptr + off) : make_float4(0, 0, 0, 0);
            rb = *(const float4*)(bptr + off);
        }

#pragma unroll
        for (int k = 0; k < BK; k++) {
            float4 a = *(const float4*)&As[k][ty * 4];
            float4 b = *(const float4*)&Bs[k][tx * 4];
            float av[4] = {a.x, a.y, a.z, a.w};
            float bv[4] = {b.x, b.y, b.z, b.w};
#pragma unroll
            for (int i = 0; i < 4; i++)
#pragma unroll
                for (int j = 0; j < 4; j++)
                    c[i][j] += av[i] * bv[j];
        }
        __syncthreads();
    }

#pragma unroll
    for (int i = 0; i < 4; i++) {
        int ml = ty * 4 + i;
        if (m0 + ml < cnt) {
            int   r     = base + m0 + ml;
            int   token = g_tok[r];
            float coef  = g_cf[r];
            float* op = out + (size_t)token * H_DIM + n0 + tx * 4;
#pragma unroll
            for (int j = 0; j < 4; j++)
                atomicAdd(op + j, coef * c[i][j]);
        }
    }
}

// ---------------- launch ----------------------------------------------------
extern "C" void kernel_launch(void* const* d_in, const int* in_sizes, int n_in,
                              void* d_out, int out_size) {
    const float* x   = (const float*)d_in[0];
    const float* gw  = (const float*)d_in[1];
    const float* ws  = (const float*)d_in[2];
    const float* w2s = (const float*)d_in[3];
    float* out = (float*)d_out;

    zero_kernel<<<2048, 256>>>(out);
    gate_kernel<<<T_TOK, 256>>>(x, gw);
    scan_kernel<<<1, 32>>>();
    scatter_kernel<<<(T_TOK + 255) / 256, 256>>>(); 

    dim3 grid1(I_DIM / BN, T_TOK / BM, N_EXP);
    gemm1_kernel<<<grid1, 256>>>(x, ws);

    dim3 grid2(H_DIM / BN, T_TOK / BM, N_EXP);
    gemm2_kernel<<<grid2, 256>>>(w2s, out);
}

// round 5
// speedup vs baseline: 1.0019x; 1.0019x over previous
#include <cuda_runtime.h>
#include <math.h>

#define T_TOK 4096
#define H_DIM 2048
#define I_DIM 2048
#define N_EXP 16
#define TOPK  2

#define BM 64
#define BN 64
#define BK 16

// ---------------- routing scratch (device globals: no allocation allowed) ---
__device__ int   g_count[N_EXP];
__device__ int   g_cursor[N_EXP];
__device__ int   g_offset[N_EXP + 1];
__device__ int   g_tids[T_TOK * TOPK];   // per-token chosen expert ids
__device__ float g_tw[T_TOK * TOPK];     // per-token normalized weights
__device__ int   g_tok[T_TOK * TOPK];    // compacted row -> token
__device__ float g_cf[T_TOK * TOPK];     // compacted row -> coef
__device__ float g_h[(size_t)T_TOK * TOPK * I_DIM];  // 64 MB hidden scratch

// ---------------- init ------------------------------------------------------
__global__ void zero_kernel(float* __restrict__ out) {
    size_t idx = (size_t)blockIdx.x * blockDim.x + threadIdx.x;
    size_t stride = (size_t)gridDim.x * blockDim.x;
    for (size_t i = idx; i < (size_t)T_TOK * H_DIM; i += stride) out[i] = 0.0f;
    if (idx < N_EXP) g_count[idx] = 0;
}

// ---------------- gating: logits -> softmax top-2 -> normalized weights -----
__global__ void gate_kernel(const float* __restrict__ x,
                            const float* __restrict__ gw) {
    int t    = blockIdx.x;
    int tid  = threadIdx.x;
    int w    = tid >> 5;
    int lane = tid & 31;
    __shared__ float logits[N_EXP];

    const float* xr = x + (size_t)t * H_DIM;
    int e0 = 2 * w, e1 = 2 * w + 1;
    const float* gr0 = gw + (size_t)e0 * H_DIM;
    const float* gr1 = gw + (size_t)e1 * H_DIM;
    float a0 = 0.f, a1 = 0.f;
    for (int h = lane; h < H_DIM; h += 32) {
        float xv = xr[h];
        a0 += xv * gr0[h];
        a1 += xv * gr1[h];
    }
#pragma unroll
    for (int o = 16; o; o >>= 1) {
        a0 += __shfl_down_sync(0xFFFFFFFFu, a0, o);
        a1 += __shfl_down_sync(0xFFFFFFFFu, a1, o);
    }
    if (lane == 0) { logits[e0] = a0; logits[e1] = a1; }
    __syncthreads();

    if (tid == 0) {
        // top-1 (strict > keeps lowest index on ties, matching lax.top_k)
        int   b0 = 0;
        float v0 = logits[0];
        for (int e = 1; e < N_EXP; e++)
            if (logits[e] > v0) { v0 = logits[e]; b0 = e; }
        int   b1 = -1;
        float v1 = -3.4e38f;
        for (int e = 0; e < N_EXP; e++) {
            if (e == b0) continue;
            if (logits[e] > v1) { v1 = logits[e]; b1 = e; }
        }
        // normalized top-2 softmax weights: w0 = 1/(1+exp(l1-l0))
        float w0 = 1.0f / (1.0f + expf(v1 - v0));
        float w1 = 1.0f - w0;
        g_tids[2 * t]     = b0;
        g_tids[2 * t + 1] = b1;
        g_tw[2 * t]       = w0;
        g_tw[2 * t + 1]   = w1;
        atomicAdd(&g_count[b0], 1);
        atomicAdd(&g_count[b1], 1);
    }
}

// ---------------- prefix scan over 16 expert counts -------------------------
__global__ void scan_kernel() {
    if (threadIdx.x == 0) {
        int s = 0;
        for (int e = 0; e < N_EXP; e++) {
            g_offset[e] = s;
            s += g_count[e];
            g_cursor[e] = 0;
        }
        g_offset[N_EXP] = s;
    }
}

// ---------------- build compacted (token, coef) lists per expert ------------
__global__ void scatter_kernel() {
    int t = blockIdx.x * blockDim.x + threadIdx.x;
    if (t >= T_TOK) return;
#pragma unroll
    for (int k = 0; k < TOPK; k++) {
        int   e   = g_tids[2 * t + k];
        float wv  = g_tw[2 * t + k];
        int   pos = atomicAdd(&g_cursor[e], 1);
        int   r   = g_offset[e] + pos;
        g_tok[r] = t;
        g_cf[r]  = wv;
    }
}

// ---------------- GEMM1: h = silu(x@Wg^T) * (x@Wu^T) per expert -------------
__global__ __launch_bounds__(256) void gemm1_kernel(const float* __restrict__ x,
                                                    const float* __restrict__ ws) {
    int e    = blockIdx.z;
    int base = g_offset[e];
    int cnt  = g_offset[e + 1] - base;
    int m0   = blockIdx.y * BM;
    if (m0 >= cnt) return;
    int n0 = blockIdx.x * BN;

    __shared__ float As[BK][BM];
    __shared__ float B1s[BK][BN];
    __shared__ float B2s[BK][BN];

    int tid  = threadIdx.x;
    int tx   = tid & 15;
    int ty   = tid >> 4;
    int lrow = tid >> 2;          // 0..63
    int kc   = (tid & 3) * 4;     // 0,4,8,12

    int arow_ok = (m0 + lrow) < cnt;
    int token   = arow_ok ? g_tok[base + m0 + lrow] : 0;

    const float* aptr  = x + (size_t)token * H_DIM + kc;
    const float* b1ptr = ws + ((size_t)e * 2 * I_DIM + (n0 + lrow)) * H_DIM + kc;
    const float* b2ptr = ws + ((size_t)e * 2 * I_DIM + I_DIM + (n0 + lrow)) * H_DIM + kc;

    float4 ra  = arow_ok ? *(const float4*)aptr : make_float4(0, 0, 0, 0);
    float4 rb1 = *(const float4*)b1ptr;
    float4 rb2 = *(const float4*)b2ptr;

    float cg[4][4] = {};
    float cu[4][4] = {};

    const int KT = H_DIM / BK;
    for (int kt = 0; kt < KT; kt++) {
        As[kc + 0][lrow] = ra.x;  As[kc + 1][lrow] = ra.y;
        As[kc + 2][lrow] = ra.z;  As[kc + 3][lrow] = ra.w;
        B1s[kc + 0][lrow] = rb1.x; B1s[kc + 1][lrow] = rb1.y;
        B1s[kc + 2][lrow] = rb1.z; B1s[kc + 3][lrow] = rb1.w;
        B2s[kc + 0][lrow] = rb2.x; B2s[kc + 1][lrow] = rb2.y;
        B2s[kc + 2][lrow] = rb2.z; B2s[kc + 3][lrow] = rb2.w;
        __syncthreads();

        if (kt + 1 < KT) {   // prefetch next K-tile while computing this one
            int off = (kt + 1) * BK;
            ra  = arow_ok ? *(const float4*)(aptr + off) : make_float4(0, 0, 0, 0);
            rb1 = *(const float4*)(b1ptr + off);
            rb2 = *(const float4*)(b2ptr + off);
        }

#pragma unroll
        for (int k = 0; k < BK; k++) {
            float4 a  = *(const float4*)&As[k][ty * 4];
            float4 b1 = *(const float4*)&B1s[k][tx * 4];
            float4 b2 = *(const float4*)&B2s[k][tx * 4];
            float av[4]  = {a.x, a.y, a.z, a.w};
            float bv1[4] = {b1.x, b1.y, b1.z, b1.w};
            float bv2[4] = {b2.x, b2.y, b2.z, b2.w};
#pragma unroll
            for (int i = 0; i < 4; i++)
#pragma unroll
                for (int j = 0; j < 4; j++) {
                    cg[i][j] += av[i] * bv1[j];
                    cu[i][j] += av[i] * bv2[j];
                }
        }
        __syncthreads();
    }

#pragma unroll
    for (int i = 0; i < 4; i++) {
        int ml = ty * 4 + i;
        if (m0 + ml < cnt) {
            int r = base + m0 + ml;
            float res[4];
#pragma unroll
            for (int j = 0; j < 4; j++) {
                float g = cg[i][j];
                float u = cu[i][j];
                float s = 1.0f / (1.0f + expf(-g));
                res[j] = g * s * u;
            }
            *(float4*)&g_h[(size_t)r * I_DIM + n0 + tx * 4] =
                make_float4(res[0], res[1], res[2], res[3]);
        }
    }
}

// ---------------- GEMM2: out[token] += coef * (h @ W2^T) --------------------
__global__ __launch_bounds__(256) void gemm2_kernel(const float* __restrict__ w2s,
                                                    float* __restrict__ out) {
    int e    = blockIdx.z;
    int base = g_offset[e];
    int cnt  = g_offset[e + 1] - base;
    int m0   = blockIdx.y * BM;
    if (m0 >= cnt) return;
    int n0 = blockIdx.x * BN;

    __shared__ float As[BK][BM];
    __shared__ float Bs[BK][BN];

    int tid  = threadIdx.x;
    int tx   = tid & 15;
    int ty   = tid >> 4;
    int lrow = tid >> 2;
    int kc   = (tid & 3) * 4;

    int arow_ok = (m0 + lrow) < cnt;
    int arow    = arow_ok ? (base + m0 + lrow) : base;

    const float* aptr = g_h + (size_t)arow * I_DIM + kc;
    const float* bptr = w2s + ((size_t)e * H_DIM + (n0 + lrow)) * I_DIM + kc;

    float4 ra = arow_ok ? *(const float4*)aptr : make_float4(0, 0, 0, 0);
    float4 rb = *(const float4*)bptr;

    float c[4][4] = {};

    const int KT = I_DIM / BK;
    for (int kt = 0; kt < KT; kt++) {
        As[kc + 0][lrow] = ra.x; As[kc + 1][lrow] = ra.y;
        As[kc + 2][lrow] = ra.z; As[kc + 3][lrow] = ra.w;
        Bs[kc + 0][lrow] = rb.x; Bs[kc + 1][lrow] = rb.y;
        Bs[kc + 2][lrow] = rb.z; Bs[kc + 3][lrow] = rb.w;
        __syncthreads();

        if (kt + 1 < KT) {
            int off = (kt + 1) * BK;
            ra = arow_ok ? *(const float4*)(aptr + off) : make_float4(0, 0, 0, 0);
            rb = *(const float4*)(bptr + off);
        }

#pragma unroll
        for (int k = 0; k < BK; k++) {
            float4 a = *(const float4*)&As[k][ty * 4];
            float4 b = *(const float4*)&Bs[k][tx * 4];
            float av[4] = {a.x, a.y, a.z, a.w};
            float bv[4] = {b.x, b.y, b.z, b.w};
#pragma unroll
            for (int i = 0; i < 4; i++)
#pragma unroll
                for (int j = 0; j < 4; j++)
                    c[i][j] += av[i] * bv[j];
        }
        __syncthreads();
    }

#pragma unroll
    for (int i = 0; i < 4; i++) {
        int ml = ty * 4 + i;
        if (m0 + ml < cnt) {
            int   r     = base + m0 + ml;
            int   token = g_tok[r];
            float coef  = g_cf[r];
            float* op = out + (size_t)token * H_DIM + n0 + tx * 4;
#pragma unroll
            for (int j = 0; j < 4; j++)
                atomicAdd(op + j, coef * c[i][j]);
        }
    }
}

// ---------------- launch ----------------------------------------------------
extern "C" void kernel_launch(void* const* d_in, const int* in_sizes, int n_in,
                              void* d_out, int out_size) {
    const float* x   = (const float*)d_in[0];
    const float* gw  = (const float*)d_in[1];
    const float* ws  = (const float*)d_in[2];
    const float* w2s = (const float*)d_in[3];
    float* out = (float*)d_out;

    zero_kernel<<<2048, 256>>>(out);
    gate_kernel<<<T_TOK, 256>>>(x, gw);
    scan_kernel<<<1, 32>>>();
    scatter_kernel<<<(T_TOK + 255) / 256, 256>>>(); 

    dim3 grid1(I_DIM / BN, T_TOK / BM, N_EXP);
    gemm1_kernel<<<grid1, 256>>>(x, ws);

    dim3 grid2(H_DIM / BN, T_TOK / BM, N_EXP);
    gemm2_kernel<<<grid2, 256>>>(w2s, out);
}

// round 7
// speedup vs baseline: 2.1704x; 2.1664x over previous
#include <cuda_runtime.h>
#include <cuda_bf16.h>
#include <cstdint>
#include <cstddef>
#include <math.h>

#define T_TOK 4096
#define H_DIM 2048
#define I_DIM 2048
#define N_EXP 16
#define TOPK  2
#define NROWS (T_TOK * TOPK)
#define HPAD  128                 // padded rows for last tiles

#define BK    16
#define KT    (H_DIM / BK)        // 128 (same for I_DIM)

// smem stage layout (bytes): 4 tiles of 128 rows x 48B (16 bf16 + pad)
#define ROWB   48
#define TILE_B 6144
#define AHI 0
#define ALO 6144
#define BHI 12288
#define BLO 18432
#define STAGE_SZ 24576            // x2 stages = 49152 = 48KB dynamic exactly

// ---------------- routing scratch -------------------------------------------
__device__ int   g_count[N_EXP];
__device__ int   g_cursor[N_EXP];
__device__ int   g_offset[N_EXP + 1];
__device__ int   g_tids[NROWS];
__device__ float g_tw[NROWS];
__device__ int   g_tok[NROWS + HPAD];
__device__ float g_cf[NROWS + HPAD];
__device__ int   g_slot[NROWS + HPAD];

// ---------------- bf16 hi/lo split operand storage --------------------------
__device__ __nv_bfloat16 xb_hi[(size_t)T_TOK * H_DIM];
__device__ __nv_bfloat16 xb_lo[(size_t)T_TOK * H_DIM];
__device__ __nv_bfloat16 wsb_hi[(size_t)N_EXP * 2 * I_DIM * H_DIM];
__device__ __nv_bfloat16 wsb_lo[(size_t)N_EXP * 2 * I_DIM * H_DIM];
__device__ __nv_bfloat16 w2b_hi[(size_t)N_EXP * H_DIM * I_DIM];
__device__ __nv_bfloat16 w2b_lo[(size_t)N_EXP * H_DIM * I_DIM];
__device__ __nv_bfloat16 hb_hi[(size_t)(NROWS + HPAD) * I_DIM];
__device__ __nv_bfloat16 hb_lo[(size_t)(NROWS + HPAD) * I_DIM];
__device__ float g_y[TOPK][(size_t)T_TOK * H_DIM];

// ---------------- helpers ----------------------------------------------------
__device__ __forceinline__ uint32_t smem_u32(const void* p) {
    uint32_t r;
    asm("{ .reg .u64 t; cvta.to.shared.u64 t, %1; cvt.u32.u64 %0, t; }"
        : "=r"(r) : "l"(p));
    return r;
}
__device__ __forceinline__ void ldm4(uint32_t a, uint32_t& r0, uint32_t& r1,
                                     uint32_t& r2, uint32_t& r3) {
    asm volatile("ldmatrix.sync.aligned.m8n8.x4.shared.b16 {%0,%1,%2,%3}, [%4];"
                 : "=r"(r0), "=r"(r1), "=r"(r2), "=r"(r3) : "r"(a));
}
__device__ __forceinline__ void mma_bf16(float* d, const uint32_t* a,
                                         uint32_t b0, uint32_t b1) {
    asm volatile(
        "mma.sync.aligned.m16n8k16.row.col.f32.bf16.bf16.f32 "
        "{%0,%1,%2,%3}, {%4,%5,%6,%7}, {%8,%9}, {%0,%1,%2,%3};"
        : "+f"(d[0]), "+f"(d[1]), "+f"(d[2]), "+f"(d[3])
        : "r"(a[0]), "r"(a[1]), "r"(a[2]), "r"(a[3]), "r"(b0), "r"(b1));
}
__device__ __forceinline__ uint32_t pack_bf16(__nv_bfloat16 a, __nv_bfloat16 b) {
    return (uint32_t)__bfloat16_as_ushort(a) |
           ((uint32_t)__bfloat16_as_ushort(b) << 16);
}

// ---------------- pre-pass: fp32 -> bf16 hi/lo split -------------------------
__global__ void cvt_split(const float* __restrict__ src,
                          __nv_bfloat16* __restrict__ hi,
                          __nv_bfloat16* __restrict__ lo, size_t n4) {
    size_t i = (size_t)blockIdx.x * blockDim.x + threadIdx.x;
    size_t stride = (size_t)gridDim.x * blockDim.x;
    const float4* s4 = (const float4*)src;
    uint32_t* h2 = (uint32_t*)hi;
    uint32_t* l2 = (uint32_t*)lo;
    for (; i < n4; i += stride) {
        float4 v = s4[i];
        __nv_bfloat16 h0 = __float2bfloat16_rn(v.x), h1 = __float2bfloat16_rn(v.y);
        __nv_bfloat16 h2b = __float2bfloat16_rn(v.z), h3 = __float2bfloat16_rn(v.w);
        float l0 = v.x - __bfloat162float(h0), l1 = v.y - __bfloat162float(h1);
        float l2f = v.z - __bfloat162float(h2b), l3 = v.w - __bfloat162float(h3);
        h2[i * 2]     = pack_bf16(h0, h1);
        h2[i * 2 + 1] = pack_bf16(h2b, h3);
        l2[i * 2]     = pack_bf16(__float2bfloat16_rn(l0), __float2bfloat16_rn(l1));
        l2[i * 2 + 1] = pack_bf16(__float2bfloat16_rn(l2f), __float2bfloat16_rn(l3));
    }
}

// ---------------- gating / scan / scatter / combine --------------------------
__global__ void init_kernel() { if (threadIdx.x < N_EXP) g_count[threadIdx.x] = 0; }

__global__ void gate_kernel(const float* __restrict__ x, const float* __restrict__ gw) {
    int t = blockIdx.x, tid = threadIdx.x, w = tid >> 5, lane = tid & 31;
    __shared__ float logits[N_EXP];
    const float* xr = x + (size_t)t * H_DIM;
    int e0 = 2 * w, e1 = 2 * w + 1;
    const float* gr0 = gw + (size_t)e0 * H_DIM;
    const float* gr1 = gw + (size_t)e1 * H_DIM;
    float a0 = 0.f, a1 = 0.f;
    for (int h = lane; h < H_DIM; h += 32) {
        float xv = xr[h];
        a0 += xv * gr0[h];
        a1 += xv * gr1[h];
    }
#pragma unroll
    for (int o = 16; o; o >>= 1) {
        a0 += __shfl_down_sync(0xFFFFFFFFu, a0, o);
        a1 += __shfl_down_sync(0xFFFFFFFFu, a1, o);
    }
    if (lane == 0) { logits[e0] = a0; logits[e1] = a1; }
    __syncthreads();
    if (tid == 0) {
        int b0 = 0; float v0 = logits[0];
        for (int e = 1; e < N_EXP; e++) if (logits[e] > v0) { v0 = logits[e]; b0 = e; }
        int b1 = -1; float v1 = -3.4e38f;
        for (int e = 0; e < N_EXP; e++) {
            if (e == b0) continue;
            if (logits[e] > v1) { v1 = logits[e]; b1 = e; }
        }
        float w0 = 1.0f / (1.0f + expf(v1 - v0));
        g_tids[2 * t] = b0;   g_tids[2 * t + 1] = b1;
        g_tw[2 * t] = w0;     g_tw[2 * t + 1] = 1.0f - w0;
        atomicAdd(&g_count[b0], 1);
        atomicAdd(&g_count[b1], 1);
    }
}

__global__ void scan_kernel() {
    if (threadIdx.x == 0) {
        int s = 0;
        for (int e = 0; e < N_EXP; e++) { g_offset[e] = s; s += g_count[e]; g_cursor[e] = 0; }
        g_offset[N_EXP] = s;
    }
}

__global__ void scatter_kernel() {
    int t = blockIdx.x * blockDim.x + threadIdx.x;
    if (t >= T_TOK) return;
#pragma unroll
    for (int k = 0; k < TOPK; k++) {
        int e = g_tids[2 * t + k];
        int pos = atomicAdd(&g_cursor[e], 1);
        int r = g_offset[e] + pos;
        g_tok[r] = t; g_cf[r] = g_tw[2 * t + k]; g_slot[r] = k;
    }
}

__global__ void combine_kernel(float* __restrict__ out) {
    size_t i = (size_t)blockIdx.x * blockDim.x + threadIdx.x;
    size_t n = (size_t)T_TOK * H_DIM / 4;
    size_t stride = (size_t)gridDim.x * blockDim.x;
    const float4* y0 = (const float4*)g_y[0];
    const float4* y1 = (const float4*)g_y[1];
    float4* o = (float4*)out;
    for (; i < n; i += stride) {
        float4 a = y0[i], b = y1[i];
        o[i] = make_float4(a.x + b.x, a.y + b.y, a.z + b.z, a.w + b.w);
    }
}

// ---------------- GEMM1: h = silu(x@Wg^T)*(x@Wu^T)  (mma.sync bf16 3-term) --
__global__ __launch_bounds__(256) void gemm1_mma() {
    const int e = blockIdx.z;
    const int base = g_offset[e];
    const int cnt = g_offset[e + 1] - base;
    const int m0 = blockIdx.y * 128;
    if (m0 >= cnt) return;
    const int n0g = blockIdx.x * 64;        // h columns [n0g, n0g+64)

    extern __shared__ __align__(16) char smem[];
    const uint32_t sb = smem_u32(smem);

    const int tid = threadIdx.x;
    const int wid = tid >> 5, lane = tid & 31;
    const int warp_m = wid >> 2, warp_n = wid & 3;

    // per-thread loader geometry: one row (t>>1), one 16B half (t&1)
    const int row = tid >> 1, half = tid & 1;
    const int arow = (m0 + row < cnt) ? base + m0 + row : base;
    const int token = g_tok[arow];
    const __nv_bfloat16* aH = xb_hi + (size_t)token * H_DIM + half * 8;
    const __nv_bfloat16* aL = xb_lo + (size_t)token * H_DIM + half * 8;
    const int brow = (row < 64) ? (n0g + row) : (I_DIM + n0g + row - 64);
    const size_t boff = ((size_t)e * 2 * I_DIM + brow) * H_DIM + half * 8;
    const __nv_bfloat16* bH = wsb_hi + boff;
    const __nv_bfloat16* bL = wsb_lo + boff;
    char* dst0 = smem + row * ROWB + half * 16;

    float acc[4][4][4];
#pragma unroll
    for (int i = 0; i < 4; i++)
#pragma unroll
        for (int j = 0; j < 4; j++)
#pragma unroll
            for (int k = 0; k < 4; k++) acc[i][j][k] = 0.f;

    uint4 pah, pal, pbh, pbl;
    pah = *(const uint4*)aH; pal = *(const uint4*)aL;
    pbh = *(const uint4*)bH; pbl = *(const uint4*)bL;
    *(uint4*)(dst0 + AHI) = pah; *(uint4*)(dst0 + ALO) = pal;
    *(uint4*)(dst0 + BHI) = pbh; *(uint4*)(dst0 + BLO) = pbl;
    __syncthreads();

#pragma unroll 1
    for (int kt = 0; kt < KT; kt++) {
        const int s = kt & 1;
        if (kt + 1 < KT) {
            pah = *(const uint4*)(aH + (kt + 1) * BK);
            pal = *(const uint4*)(aL + (kt + 1) * BK);
            pbh = *(const uint4*)(bH + (kt + 1) * BK);
            pbl = *(const uint4*)(bL + (kt + 1) * BK);
        }
        // ---- compute on stage s ----
        {
            const uint32_t st = sb + s * STAGE_SZ;
            const uint32_t lrow = (lane & 15), lchunk = (lane >> 4) * 16;
            uint32_t bh[2][4], bl[2][4];
#pragma unroll
            for (int p = 0; p < 2; p++) {
                uint32_t ba = st + BHI + (warp_n * 32 + p * 16 + lrow) * ROWB + lchunk;
                ldm4(ba, bh[p][0], bh[p][1], bh[p][2], bh[p][3]);
                ldm4(ba + (BLO - BHI), bl[p][0], bl[p][1], bl[p][2], bl[p][3]);
            }
#pragma unroll
            for (int mf = 0; mf < 4; mf++) {
                uint32_t ah[4], al[4];
                uint32_t aa = st + AHI + (warp_m * 64 + mf * 16 + lrow) * ROWB + lchunk;
                ldm4(aa, ah[0], ah[1], ah[2], ah[3]);
                ldm4(aa + (ALO - AHI), al[0], al[1], al[2], al[3]);
#pragma unroll
                for (int nf = 0; nf < 4; nf++) {
                    const int p = nf >> 1, q = nf & 1;
                    mma_bf16(acc[mf][nf], ah, bh[p][q], bh[p][q + 2]);
                    mma_bf16(acc[mf][nf], ah, bl[p][q], bl[p][q + 2]);
                    mma_bf16(acc[mf][nf], al, bh[p][q], bh[p][q + 2]);
                }
            }
        }
        __syncthreads();
        if (kt + 1 < KT) {
            char* d = dst0 + (s ^ 1) * STAGE_SZ;
            *(uint4*)(d + AHI) = pah; *(uint4*)(d + ALO) = pal;
            *(uint4*)(d + BHI) = pbh; *(uint4*)(d + BLO) = pbl;
            __syncthreads();
        }
    }

    // ---- epilogue: exchange gate via smem, fused SiLU, write bf16 h --------
    __syncthreads();
    float* sg = (float*)smem;            // [128][68]
    const int qr = lane >> 2, qc = (lane & 3) * 2;
    if (warp_n < 2) {
#pragma unroll
        for (int mf = 0; mf < 4; mf++)
#pragma unroll
            for (int nf = 0; nf < 4; nf++) {
                int r = warp_m * 64 + mf * 16 + qr;
                int c = warp_n * 32 + nf * 8 + qc;
                sg[r * 68 + c]       = acc[mf][nf][0];
                sg[r * 68 + c + 1]   = acc[mf][nf][1];
                sg[(r + 8) * 68 + c]     = acc[mf][nf][2];
                sg[(r + 8) * 68 + c + 1] = acc[mf][nf][3];
            }
    }
    __syncthreads();
    if (warp_n >= 2) {
#pragma unroll
        for (int mf = 0; mf < 4; mf++)
#pragma unroll
            for (int nf = 0; nf < 4; nf++) {
                int r = warp_m * 64 + mf * 16 + qr;
                int cu = (warp_n - 2) * 32 + nf * 8 + qc;
#pragma unroll
                for (int rr = 0; rr < 2; rr++) {
                    int rloc = r + rr * 8;
                    if (m0 + rloc < cnt) {
                        float g0 = sg[rloc * 68 + cu];
                        float g1 = sg[rloc * 68 + cu + 1];
                        float u0 = acc[mf][nf][rr * 2];
                        float u1 = acc[mf][nf][rr * 2 + 1];
                        float h0 = g0 / (1.0f + expf(-g0)) * u0;
                        float h1 = g1 / (1.0f + expf(-g1)) * u1;
                        size_t idx = (size_t)(base + m0 + rloc) * I_DIM + n0g + cu;
                        __nv_bfloat16 b0 = __float2bfloat16_rn(h0);
                        __nv_bfloat16 b1 = __float2bfloat16_rn(h1);
                        float l0 = h0 - __bfloat162float(b0);
                        float l1 = h1 - __bfloat162float(b1);
                        *(uint32_t*)(hb_hi + idx) = pack_bf16(b0, b1);
                        *(uint32_t*)(hb_lo + idx) =
                            pack_bf16(__float2bfloat16_rn(l0), __float2bfloat16_rn(l1));
                    }
                }
            }
    }
}

// ---------------- GEMM2: y[slot] = coef * (h @ W2^T) ------------------------
__global__ __launch_bounds__(256) void gemm2_mma() {
    const int e = blockIdx.z;
    const int base = g_offset[e];
    const int cnt = g_offset[e + 1] - base;
    const int m0 = blockIdx.y * 128;
    if (m0 >= cnt) return;
    const int n0 = blockIdx.x * 128;

    extern __shared__ __align__(16) char smem[];
    const uint32_t sb = smem_u32(smem);

    const int tid = threadIdx.x;
    const int wid = tid >> 5, lane = tid & 31;
    const int warp_m = wid >> 2, warp_n = wid & 3;

    const int row = tid >> 1, half = tid & 1;
    const int ridx = (m0 + row < cnt) ? base + m0 + row : base;
    const __nv_bfloat16* aH = hb_hi + (size_t)ridx * I_DIM + half * 8;
    const __nv_bfloat16* aL = hb_lo + (size_t)ridx * I_DIM + half * 8;
    const size_t boff = ((size_t)e * H_DIM + n0 + row) * I_DIM + half * 8;
    const __nv_bfloat16* bH = w2b_hi + boff;
    const __nv_bfloat16* bL = w2b_lo + boff;
    char* dst0 = smem + row * ROWB + half * 16;

    float acc[4][4][4];
#pragma unroll
    for (int i = 0; i < 4; i++)
#pragma unroll
        for (int j = 0; j < 4; j++)
#pragma unroll
            for (int k = 0; k < 4; k++) acc[i][j][k] = 0.f;

    uint4 pah, pal, pbh, pbl;
    pah = *(const uint4*)aH; pal = *(const uint4*)aL;
    pbh = *(const uint4*)bH; pbl = *(const uint4*)bL;
    *(uint4*)(dst0 + AHI) = pah; *(uint4*)(dst0 + ALO) = pal;
    *(uint4*)(dst0 + BHI) = pbh; *(uint4*)(dst0 + BLO) = pbl;
    __syncthreads();

#pragma unroll 1
    for (int kt = 0; kt < KT; kt++) {
        const int s = kt & 1;
        if (kt + 1 < KT) {
            pah = *(const uint4*)(aH + (kt + 1) * BK);
            pal = *(const uint4*)(aL + (kt + 1) * BK);
            pbh = *(const uint4*)(bH + (kt + 1) * BK);
            pbl = *(const uint4*)(bL + (kt + 1) * BK);
        }
        {
            const uint32_t st = sb + s * STAGE_SZ;
            const uint32_t lrow = (lane & 15), lchunk = (lane >> 4) * 16;
            uint32_t bh[2][4], bl[2][4];
#pragma unroll
            for (int p = 0; p < 2; p++) {
                uint32_t ba = st + BHI + (warp_n * 32 + p * 16 + lrow) * ROWB + lchunk;
                ldm4(ba, bh[p][0], bh[p][1], bh[p][2], bh[p][3]);
                ldm4(ba + (BLO - BHI), bl[p][0], bl[p][1], bl[p][2], bl[p][3]);
            }
#pragma unroll
            for (int mf = 0; mf < 4; mf++) {
                uint32_t ah[4], al[4];
                uint32_t aa = st + AHI + (warp_m * 64 + mf * 16 + lrow) * ROWB + lchunk;
                ldm4(aa, ah[0], ah[1], ah[2], ah[3]);
                ldm4(aa + (ALO - AHI), al[0], al[1], al[2], al[3]);
#pragma unroll
                for (int nf = 0; nf < 4; nf++) {
                    const int p = nf >> 1, q = nf & 1;
                    mma_bf16(acc[mf][nf], ah, bh[p][q], bh[p][q + 2]);
                    mma_bf16(acc[mf][nf], ah, bl[p][q], bl[p][q + 2]);
                    mma_bf16(acc[mf][nf], al, bh[p][q], bh[p][q + 2]);
                }
            }
        }
        __syncthreads();
        if (kt + 1 < KT) {
            char* d = dst0 + (s ^ 1) * STAGE_SZ;
            *(uint4*)(d + AHI) = pah; *(uint4*)(d + ALO) = pal;
            *(uint4*)(d + BHI) = pbh; *(uint4*)(d + BLO) = pbl;
            __syncthreads();
        }
    }

    // ---- epilogue: coef-scaled write into per-slot buffer -------------------
    const int qr = lane >> 2, qc = (lane & 3) * 2;
#pragma unroll
    for (int mf = 0; mf < 4; mf++) {
#pragma unroll
        for (int rr = 0; rr < 2; rr++) {
            int r = warp_m * 64 + mf * 16 + qr + rr * 8;
            if (m0 + r < cnt) {
                int gi = base + m0 + r;
                int token = g_tok[gi];
                float coef = g_cf[gi];
                float* yrow = g_y[g_slot[gi]] + (size_t)token * H_DIM + n0;
#pragma unroll
                for (int nf = 0; nf < 4; nf++) {
                    int c = warp_n * 32 + nf * 8 + qc;
                    float2 v;
                    v.x = coef * acc[mf][nf][rr * 2];
                    v.y = coef * acc[mf][nf][rr * 2 + 1];
                    *(float2*)(yrow + c) = v;
                }
            }
        }
    }
}

// ---------------- launch ----------------------------------------------------
extern "C" void kernel_launch(void* const* d_in, const int* in_sizes, int n_in,
                              void* d_out, int out_size) {
    const float* x = (const float*)d_in[0];
    const float* gw = (const float*)d_in[1];
    const float* ws = (const float*)d_in[2];
    const float* w2s = (const float*)d_in[3];
    float* out = (float*)d_out;

    __nv_bfloat16 *p_xh, *p_xl, *p_wh, *p_wl, *p_2h, *p_2l;
    cudaGetSymbolAddress((void**)&p_xh, xb_hi);
    cudaGetSymbolAddress((void**)&p_xl, xb_lo);
    cudaGetSymbolAddress((void**)&p_wh, wsb_hi);
    cudaGetSymbolAddress((void**)&p_wl, wsb_lo);
    cudaGetSymbolAddress((void**)&p_2h, w2b_hi);
    cudaGetSymbolAddress((void**)&p_2l, w2b_lo);

    init_kernel<<<1, 32>>>();
    gate_kernel<<<T_TOK, 256>>>(x, gw);
    scan_kernel<<<1, 32>>>();
    scatter_kernel<<<(T_TOK + 255) / 256, 256>>>();

    cvt_split<<<2048, 256>>>(x,  p_xh, p_xl, (size_t)T_TOK * H_DIM / 4);
    cvt_split<<<4096, 256>>>(ws, p_wh, p_wl, (size_t)N_EXP * 2 * I_DIM * H_DIM / 4);
    cvt_split<<<4096, 256>>>(w2s, p_2h, p_2l, (size_t)N_EXP * H_DIM * I_DIM / 4);

    dim3 grid1(I_DIM / 64, NROWS / 128, N_EXP);
    gemm1_mma<<<grid1, 256, 2 * STAGE_SZ>>>();

    dim3 grid2(H_DIM / 128, NROWS / 128, N_EXP);
    gemm2_mma<<<grid2, 256, 2 * STAGE_SZ>>>();

    combine_kernel<<<2048, 256>>>(out);
}

// round 10
// speedup vs baseline: 2.6088x; 1.2020x over previous
#include <cuda_runtime.h>
#include <cuda_bf16.h>
#include <cstdint>
#include <cstddef>
#include <math.h>

#define T_TOK 4096
#define H_DIM 2048
#define I_DIM 2048
#define N_EXP 16
#define TOPK  2
#define NROWS (T_TOK * TOPK)
#define HPAD  128

#define BK32   32
#define KT32   (H_DIM / BK32)     // 64
#define NSTG   3
#define TILE_SZ 16384u            // 128 rows x 128B (hi|lo interleaved)
#define STAGE_SZ 32768u           // A tile + B tile
#define SMEM_DYN (NSTG * STAGE_SZ)

// ---------------- routing scratch -------------------------------------------
__device__ int   g_count[N_EXP];
__device__ int   g_cursor[N_EXP];
__device__ int   g_offset[N_EXP + 1];
__device__ int   g_tids[NROWS];
__device__ float g_tw[NROWS];
__device__ int   g_tok[NROWS + HPAD];
__device__ float g_cf[NROWS + HPAD];
__device__ int   g_slot[NROWS + HPAD];

// ---------------- bf16 hi/lo split operand storage --------------------------
__device__ __nv_bfloat16 xb_hi[(size_t)T_TOK * H_DIM];
__device__ __nv_bfloat16 xb_lo[(size_t)T_TOK * H_DIM];
__device__ __nv_bfloat16 wsb_hi[(size_t)N_EXP * 2 * I_DIM * H_DIM];
__device__ __nv_bfloat16 wsb_lo[(size_t)N_EXP * 2 * I_DIM * H_DIM];
__device__ __nv_bfloat16 w2b_hi[(size_t)N_EXP * H_DIM * I_DIM];
__device__ __nv_bfloat16 w2b_lo[(size_t)N_EXP * H_DIM * I_DIM];
__device__ __nv_bfloat16 hb_hi[(size_t)(NROWS + HPAD) * I_DIM];
__device__ __nv_bfloat16 hb_lo[(size_t)(NROWS + HPAD) * I_DIM];
__device__ float g_y[TOPK][(size_t)T_TOK * H_DIM];

// ---------------- helpers ----------------------------------------------------
__device__ __forceinline__ uint32_t smem_u32(const void* p) {
    uint32_t r;
    asm("{ .reg .u64 t; cvta.to.shared.u64 t, %1; cvt.u32.u64 %0, t; }"
        : "=r"(r) : "l"(p));
    return r;
}
__device__ __forceinline__ void ldm4(uint32_t a, uint32_t& r0, uint32_t& r1,
                                     uint32_t& r2, uint32_t& r3) {
    asm volatile("ldmatrix.sync.aligned.m8n8.x4.shared.b16 {%0,%1,%2,%3}, [%4];"
                 : "=r"(r0), "=r"(r1), "=r"(r2), "=r"(r3) : "r"(a));
}
__device__ __forceinline__ void mma_bf16(float* d, const uint32_t* a,
                                         uint32_t b0, uint32_t b1) {
    asm volatile(
        "mma.sync.aligned.m16n8k16.row.col.f32.bf16.bf16.f32 "
        "{%0,%1,%2,%3}, {%4,%5,%6,%7}, {%8,%9}, {%0,%1,%2,%3};"
        : "+f"(d[0]), "+f"(d[1]), "+f"(d[2]), "+f"(d[3])
        : "r"(a[0]), "r"(a[1]), "r"(a[2]), "r"(a[3]), "r"(b0), "r"(b1));
}
__device__ __forceinline__ uint32_t pack_bf16(__nv_bfloat16 a, __nv_bfloat16 b) {
    return (uint32_t)__bfloat16_as_ushort(a) |
           ((uint32_t)__bfloat16_as_ushort(b) << 16);
}
__device__ __forceinline__ void cp16(uint32_t dst, const void* src) {
    asm volatile("cp.async.cg.shared.global [%0], [%1], 16;" :: "r"(dst), "l"(src) : "memory");
}
#define CP_COMMIT() asm volatile("cp.async.commit_group;" ::: "memory")
#define CP_WAIT1()  asm volatile("cp.async.wait_group 1;" ::: "memory")
#define CP_WAIT0()  asm volatile("cp.async.wait_group 0;" ::: "memory")

// ---------------- pre-pass: fp32 -> bf16 hi/lo split -------------------------
__global__ void cvt_split(const float* __restrict__ src,
                          __nv_bfloat16* __restrict__ hi,
                          __nv_bfloat16* __restrict__ lo, size_t n4) {
    size_t i = (size_t)blockIdx.x * blockDim.x + threadIdx.x;
    size_t stride = (size_t)gridDim.x * blockDim.x;
    const float4* s4 = (const float4*)src;
    uint2* h2 = (uint2*)hi;
    uint2* l2 = (uint2*)lo;
    for (; i < n4; i += stride) {
        float4 v = s4[i];
        __nv_bfloat16 h0 = __float2bfloat16_rn(v.x), h1 = __float2bfloat16_rn(v.y);
        __nv_bfloat16 h2b = __float2bfloat16_rn(v.z), h3 = __float2bfloat16_rn(v.w);
        float l0 = v.x - __bfloat162float(h0), l1 = v.y - __bfloat162float(h1);
        float l2f = v.z - __bfloat162float(h2b), l3 = v.w - __bfloat162float(h3);
        uint2 ph; ph.x = pack_bf16(h0, h1); ph.y = pack_bf16(h2b, h3);
        uint2 pl;
        pl.x = pack_bf16(__float2bfloat16_rn(l0), __float2bfloat16_rn(l1));
        pl.y = pack_bf16(__float2bfloat16_rn(l2f), __float2bfloat16_rn(l3));
        h2[i] = ph;
        l2[i] = pl;
    }
}

// ---------------- gating: tiled 16 tokens x 16 experts -----------------------
__global__ __launch_bounds__(256) void gate_kernel(const float* __restrict__ x,
                                                   const float* __restrict__ gw) {
    __shared__ __align__(16) float xs[16][132];
    __shared__ __align__(16) float gs[16][132];
    __shared__ float lg[16][17];

    int tid = threadIdx.x;
    int t0  = blockIdx.x * 16;
    int tok = tid >> 4;
    int e   = tid & 15;
    float acc = 0.f;

    for (int kc = 0; kc < H_DIM; kc += 128) {
        __syncthreads();
        for (int i = tid; i < 512; i += 256) {
            int r = i >> 5, c4 = i & 31;
            *(float4*)&xs[r][c4 * 4] =
                *(const float4*)(x + (size_t)(t0 + r) * H_DIM + kc + c4 * 4);
            *(float4*)&gs[r][c4 * 4] =
                *(const float4*)(gw + (size_t)r * H_DIM + kc + c4 * 4);
        }
        __syncthreads();
#pragma unroll 16
        for (int k = 0; k < 128; k++) acc += xs[tok][k] * gs[e][k];
    }
    lg[tok][e] = acc;
    __syncthreads();

    if (tid < 16) {
        int t = t0 + tid;
        int b0 = 0; float v0 = lg[tid][0];
        for (int j = 1; j < N_EXP; j++)
            if (lg[tid][j] > v0) { v0 = lg[tid][j]; b0 = j; }
        int b1 = -1; float v1 = -3.4e38f;
        for (int j = 0; j < N_EXP; j++) {
            if (j == b0) continue;
            if (lg[tid][j] > v1) { v1 = lg[tid][j]; b1 = j; }
        }
        float w0 = 1.0f / (1.0f + expf(v1 - v0));
        g_tids[2 * t] = b0;   g_tids[2 * t + 1] = b1;
        g_tw[2 * t] = w0;     g_tw[2 * t + 1] = 1.0f - w0;
        atomicAdd(&g_count[b0], 1);
        atomicAdd(&g_count[b1], 1);
    }
}

// ---------------- misc small kernels -----------------------------------------
__global__ void init_kernel() { if (threadIdx.x < N_EXP) g_count[threadIdx.x] = 0; }

__global__ void scan_kernel() {
    if (threadIdx.x == 0) {
        int s = 0;
        for (int e = 0; e < N_EXP; e++) { g_offset[e] = s; s += g_count[e]; g_cursor[e] = 0; }
        g_offset[N_EXP] = s;
    }
}

__global__ void scatter_kernel() {
    int t = blockIdx.x * blockDim.x + threadIdx.x;
    if (t >= T_TOK) return;
#pragma unroll
    for (int k = 0; k < TOPK; k++) {
        int e = g_tids[2 * t + k];
        int pos = atomicAdd(&g_cursor[e], 1);
        int r = g_offset[e] + pos;
        g_tok[r] = t; g_cf[r] = g_tw[2 * t + k]; g_slot[r] = k;
    }
}

__global__ void combine_kernel(float* __restrict__ out) {
    size_t i = (size_t)blockIdx.x * blockDim.x + threadIdx.x;
    size_t n = (size_t)T_TOK * H_DIM / 4;
    size_t stride = (size_t)gridDim.x * blockDim.x;
    const float4* y0 = (const float4*)g_y[0];
    const float4* y1 = (const float4*)g_y[1];
    float4* o = (float4*)out;
    for (; i < n; i += stride) {
        float4 a = y0[i], b = y1[i];
        o[i] = make_float4(a.x + b.x, a.y + b.y, a.z + b.z, a.w + b.w);
    }
}

// swizzled in-tile byte offset for (row, chunk16B)
__device__ __forceinline__ uint32_t tof(int row, int ch) {
    return (uint32_t)(row * 128 + ((ch ^ (row & 7)) * 16));
}

// ---------------- GEMM1: h = silu(x@Wg^T)*(x@Wu^T) ---------------------------
__global__ __launch_bounds__(256, 2) void gemm1_mma() {
    const int e = blockIdx.z;
    const int base = g_offset[e];
    const int cnt = g_offset[e + 1] - base;
    const int m0 = blockIdx.y * 128;
    if (m0 >= cnt) return;
    const int n0g = blockIdx.x * 64;

    extern __shared__ __align__(16) char smem[];
    __shared__ int s_tok[128];
    const uint32_t sb = smem_u32(smem);

    const int tid = threadIdx.x;
    const int wid = tid >> 5, lane = tid & 31;
    const int warp_m = wid >> 2, warp_n = wid & 3;

    if (tid < 128) s_tok[tid] = (m0 + tid < cnt) ? g_tok[base + m0 + tid] : g_tok[base];
    __syncthreads();

    // loader geometry: 4 rows per tile per thread, fixed 16B chunk
    const int rbase = tid >> 3;          // 0..31
    const int ch    = tid & 7;           // 0..7 ; <4 = hi, >=4 = lo
    const int kch   = ch & 3;
    const bool isLo = ch >= 4;
    const __nv_bfloat16* asrc[4];
    const __nv_bfloat16* bsrc[4];
    uint32_t dA[4], dB[4];
#pragma unroll
    for (int j = 0; j < 4; j++) {
        int row = rbase + j * 32;
        asrc[j] = (isLo ? xb_lo : xb_hi) + (size_t)s_tok[row] * H_DIM + kch * 8;
        int brow = (row < 64) ? (n0g + row) : (I_DIM + n0g + row - 64);
        bsrc[j] = (isLo ? wsb_lo : wsb_hi) +
                  ((size_t)e * 2 * I_DIM + brow) * H_DIM + kch * 8;
        uint32_t off = tof(row, ch);
        dA[j] = off;
        dB[j] = TILE_SZ + off;
    }

    float acc[4][4][4];
#pragma unroll
    for (int i = 0; i < 4; i++)
#pragma unroll
        for (int j = 0; j < 4; j++)
#pragma unroll
            for (int k = 0; k < 4; k++) acc[i][j][k] = 0.f;

    auto load_stage = [&](int slot, int kt) {
        uint32_t stb = sb + (uint32_t)slot * STAGE_SZ;
#pragma unroll
        for (int j = 0; j < 4; j++) {
            cp16(stb + dA[j], asrc[j] + kt * BK32);
            cp16(stb + dB[j], bsrc[j] + kt * BK32);
        }
        CP_COMMIT();
    };

    load_stage(0, 0);
    load_stage(1, 1);

    const int lrow = lane & 15, lhalf = lane >> 4;

#pragma unroll 1
    for (int kt = 0; kt < KT32; kt++) {
        if (kt + 1 < KT32) CP_WAIT1(); else CP_WAIT0();
        __syncthreads();
        if (kt + 2 < KT32) load_stage((kt + 2) % NSTG, kt + 2);

        const uint32_t st = sb + (uint32_t)(kt % NSTG) * STAGE_SZ;
#pragma unroll
        for (int s = 0; s < 2; s++) {
            uint32_t bh[2][4], bl[2][4];
#pragma unroll
            for (int p = 0; p < 2; p++) {
                int row = warp_n * 32 + p * 16 + lrow;
                ldm4(st + TILE_SZ + tof(row, 2 * s + lhalf),
                     bh[p][0], bh[p][1], bh[p][2], bh[p][3]);
                ldm4(st + TILE_SZ + tof(row, 4 + 2 * s + lhalf),
                     bl[p][0], bl[p][1], bl[p][2], bl[p][3]);
            }
#pragma unroll
            for (int mf = 0; mf < 4; mf++) {
                int row = warp_m * 64 + mf * 16 + lrow;
                uint32_t ah[4], al[4];
                ldm4(st + tof(row, 2 * s + lhalf), ah[0], ah[1], ah[2], ah[3]);
                ldm4(st + tof(row, 4 + 2 * s + lhalf), al[0], al[1], al[2], al[3]);
#pragma unroll
                for (int nf = 0; nf < 4; nf++) {
                    const int p = nf >> 1, q = nf & 1;
                    mma_bf16(acc[mf][nf], ah, bh[p][q], bh[p][q + 2]);
                    mma_bf16(acc[mf][nf], ah, bl[p][q], bl[p][q + 2]);
                    mma_bf16(acc[mf][nf], al, bh[p][q], bh[p][q + 2]);
                }
            }
        }
    }

    // ---- epilogue: exchange gate via smem, fused SiLU, write bf16 h --------
    __syncthreads();
    float* sg = (float*)smem;            // [128][68]
    const int qr = lane >> 2, qc = (lane & 3) * 2;
    if (warp_n < 2) {
#pragma unroll
        for (int mf = 0; mf < 4; mf++)
#pragma unroll
            for (int nf = 0; nf < 4; nf++) {
                int r = warp_m * 64 + mf * 16 + qr;
                int c = warp_n * 32 + nf * 8 + qc;
                sg[r * 68 + c]           = acc[mf][nf][0];
                sg[r * 68 + c + 1]       = acc[mf][nf][1];
                sg[(r + 8) * 68 + c]     = acc[mf][nf][2];
                sg[(r + 8) * 68 + c + 1] = acc[mf][nf][3];
            }
    }
    __syncthreads();
    if (warp_n >= 2) {
#pragma unroll
        for (int mf = 0; mf < 4; mf++)
#pragma unroll
            for (int nf = 0; nf < 4; nf++) {
                int r = warp_m * 64 + mf * 16 + qr;
                int cu = (warp_n - 2) * 32 + nf * 8 + qc;
#pragma unroll
                for (int rr = 0; rr < 2; rr++) {
                    int rloc = r + rr * 8;
                    if (m0 + rloc < cnt) {
                        float g0 = sg[rloc * 68 + cu];
                        float g1 = sg[rloc * 68 + cu + 1];
                        float u0 = acc[mf][nf][rr * 2];
                        float u1 = acc[mf][nf][rr * 2 + 1];
                        float h0 = g0 / (1.0f + expf(-g0)) * u0;
                        float h1 = g1 / (1.0f + expf(-g1)) * u1;
                        size_t idx = (size_t)(base + m0 + rloc) * I_DIM + n0g + cu;
                        __nv_bfloat16 b0 = __float2bfloat16_rn(h0);
                        __nv_bfloat16 b1 = __float2bfloat16_rn(h1);
                        float l0 = h0 - __bfloat162float(b0);
                        float l1 = h1 - __bfloat162float(b1);
                        *(uint32_t*)(hb_hi + idx) = pack_bf16(b0, b1);
                        *(uint32_t*)(hb_lo + idx) =
                            pack_bf16(__float2bfloat16_rn(l0), __float2bfloat16_rn(l1));
                    }
                }
            }
    }
}

// ---------------- GEMM2: y[slot] = coef * (h @ W2^T) -------------------------
__global__ __launch_bounds__(256, 2) void gemm2_mma() {
    const int e = blockIdx.z;
    const int base = g_offset[e];
    const int cnt = g_offset[e + 1] - base;
    const int m0 = blockIdx.y * 128;
    if (m0 >= cnt) return;
    const int n0 = blockIdx.x * 128;

    extern __shared__ __align__(16) char smem[];
    const uint32_t sb = smem_u32(smem);

    const int tid = threadIdx.x;
    const int wid = tid >> 5, lane = tid & 31;
    const int warp_m = wid >> 2, warp_n = wid & 3;

    const int rbase = tid >> 3;
    const int ch    = tid & 7;
    const int kch   = ch & 3;
    const bool isLo = ch >= 4;
    const __nv_bfloat16* asrc[4];
    const __nv_bfloat16* bsrc[4];
    uint32_t dA[4], dB[4];
#pragma unroll
    for (int j = 0; j < 4; j++) {
        int row = rbase + j * 32;
        int ridx = (m0 + row < cnt) ? (base + m0 + row) : base;
        asrc[j] = (isLo ? hb_lo : hb_hi) + (size_t)ridx * I_DIM + kch * 8;
        bsrc[j] = (isLo ? w2b_lo : w2b_hi) +
                  ((size_t)e * H_DIM + n0 + row) * I_DIM + kch * 8;
        uint32_t off = tof(row, ch);
        dA[j] = off;
        dB[j] = TILE_SZ + off;
    }

    float acc[4][4][4];
#pragma unroll
    for (int i = 0; i < 4; i++)
#pragma unroll
        for (int j = 0; j < 4; j++)
#pragma unroll
            for (int k = 0; k < 4; k++) acc[i][j][k] = 0.f;

    auto load_stage = [&](int slot, int kt) {
        uint32_t stb = sb + (uint32_t)slot * STAGE_SZ;
#pragma unroll
        for (int j = 0; j < 4; j++) {
            cp16(stb + dA[j], asrc[j] + kt * BK32);
            cp16(stb + dB[j], bsrc[j] + kt * BK32);
        }
        CP_COMMIT();
    };

    load_stage(0, 0);
    load_stage(1, 1);

    const int lrow = lane & 15, lhalf = lane >> 4;

#pragma unroll 1
    for (int kt = 0; kt < KT32; kt++) {
        if (kt + 1 < KT32) CP_WAIT1(); else CP_WAIT0();
        __syncthreads();
        if (kt + 2 < KT32) load_stage((kt + 2) % NSTG, kt + 2);

        const uint32_t st = sb + (uint32_t)(kt % NSTG) * STAGE_SZ;
#pragma unroll
        for (int s = 0; s < 2; s++) {
            uint32_t bh[2][4], bl[2][4];
#pragma unroll
            for (int p = 0; p < 2; p++) {
                int row = warp_n * 32 + p * 16 + lrow;
                ldm4(st + TILE_SZ + tof(row, 2 * s + lhalf),
                     bh[p][0], bh[p][1], bh[p][2], bh[p][3]);
                ldm4(st + TILE_SZ + tof(row, 4 + 2 * s + lhalf),
                     bl[p][0], bl[p][1], bl[p][2], bl[p][3]);
            }
#pragma unroll
            for (int mf = 0; mf < 4; mf++) {
                int row = warp_m * 64 + mf * 16 + lrow;
                uint32_t ah[4], al[4];
                ldm4(st + tof(row, 2 * s + lhalf), ah[0], ah[1], ah[2], ah[3]);
                ldm4(st + tof(row, 4 + 2 * s + lhalf), al[0], al[1], al[2], al[3]);
#pragma unroll
                for (int nf = 0; nf < 4; nf++) {
                    const int p = nf >> 1, q = nf & 1;
                    mma_bf16(acc[mf][nf], ah, bh[p][q], bh[p][q + 2]);
                    mma_bf16(acc[mf][nf], ah, bl[p][q], bl[p][q + 2]);
                    mma_bf16(acc[mf][nf], al, bh[p][q], bh[p][q + 2]);
                }
            }
        }
    }

    // ---- epilogue: coef-scaled write into per-slot buffer -------------------
    const int qr = lane >> 2, qc = (lane & 3) * 2;
#pragma unroll
    for (int mf = 0; mf < 4; mf++) {
#pragma unroll
        for (int rr = 0; rr < 2; rr++) {
            int r = warp_m * 64 + mf * 16 + qr + rr * 8;
            if (m0 + r < cnt) {
                int gi = base + m0 + r;
                int token = g_tok[gi];
                float coef = g_cf[gi];
                float* yrow = g_y[g_slot[gi]] + (size_t)token * H_DIM + n0;
#pragma unroll
                for (int nf = 0; nf < 4; nf++) {
                    int c = warp_n * 32 + nf * 8 + qc;
                    float2 v;
                    v.x = coef * acc[mf][nf][rr * 2];
                    v.y = coef * acc[mf][nf][rr * 2 + 1];
                    *(float2*)(yrow + c) = v;
                }
            }
        }
    }
}

// ---------------- launch ----------------------------------------------------
extern "C" void kernel_launch(void* const* d_in, const int* in_sizes, int n_in,
                              void* d_out, int out_size) {
    const float* x = (const float*)d_in[0];
    const float* gw = (const float*)d_in[1];
    const float* ws = (const float*)d_in[2];
    const float* w2s = (const float*)d_in[3];
    float* out = (float*)d_out;

    cudaFuncSetAttribute(gemm1_mma, cudaFuncAttributeMaxDynamicSharedMemorySize, SMEM_DYN);
    cudaFuncSetAttribute(gemm2_mma, cudaFuncAttributeMaxDynamicSharedMemorySize, SMEM_DYN);

    __nv_bfloat16 *p_xh, *p_xl, *p_wh, *p_wl, *p_2h, *p_2l;
    cudaGetSymbolAddress((void**)&p_xh, xb_hi);
    cudaGetSymbolAddress((void**)&p_xl, xb_lo);
    cudaGetSymbolAddress((void**)&p_wh, wsb_hi);
    cudaGetSymbolAddress((void**)&p_wl, wsb_lo);
    cudaGetSymbolAddress((void**)&p_2h, w2b_hi);
    cudaGetSymbolAddress((void**)&p_2l, w2b_lo);

    init_kernel<<<1, 32>>>();
    gate_kernel<<<T_TOK / 16, 256>>>(x, gw);
    scan_kernel<<<1, 32>>>();
    scatter_kernel<<<(T_TOK + 255) / 256, 256>>>();

    cvt_split<<<2048, 256>>>(x,   p_xh, p_xl, (size_t)T_TOK * H_DIM / 4);
    cvt_split<<<4096, 256>>>(ws,  p_wh, p_wl, (size_t)N_EXP * 2 * I_DIM * H_DIM / 4);
    cvt_split<<<4096, 256>>>(w2s, p_2h, p_2l, (size_t)N_EXP * H_DIM * I_DIM / 4);

    dim3 grid1(I_DIM / 64, NROWS / 128, N_EXP);
    gemm1_mma<<<grid1, 256, SMEM_DYN>>>();

    dim3 grid2(H_DIM / 128, NROWS / 128, N_EXP);
    gemm2_mma<<<grid2, 256, SMEM_DYN>>>();

    combine_kernel<<<2048, 256>>>(out);
}